// round 12
// baseline (speedup 1.0000x reference)
#include <cuda_runtime.h>
#include <cuda_bf16.h>
#include <stdint.h>

#define K_TOTAL 4096
#define N_TOTAL 11008
#define M_TOTAL 512
#define RNK 16

// ---- GEMM tiling ----
#define GM 128
#define GN 64
#define KC 64
#define NCH (K_TOTAL / KC)          /* 64 */
#define A_STAGES 3
#define A_BYTES (GM * KC * 2)       /* 16384 */
#define B_BYTES (GN * KC * 2)       /* 8192 */
#define SB_OFF (A_STAGES * A_BYTES)            /* 49152 */
#define SMEM_TOTAL (SB_OFF + 2 * B_BYTES)      /* 65536 */

// ---- xa split-K ----
#define KSPLIT 8
#define KRANGE (K_TOTAL / KSPLIT)   /* 512 */
#define KPAD 520

// ---- scratch ----
__device__ __align__(256) __nv_bfloat16 g_xb[(size_t)M_TOTAL * K_TOTAL]; // 4MB x bf16
__device__ __align__(256) float g_xap[KSPLIT * M_TOTAL * RNK];
__device__ __align__(256) float g_xa[M_TOTAL * RNK];

__constant__ float c_nf4[16] = {
    -1.0f, -0.6961928009986877f, -0.5250730514526367f, -0.39491748809814453f,
    -0.28444138169288635f, -0.18477343022823334f, -0.09105003625154495f, 0.0f,
    0.07958029955625534f, 0.16093020141124725f, 0.24611230194568634f,
    0.33791524171829224f, 0.44070982933044434f, 0.5626170039176941f,
    0.7229568362236023f, 1.0f };

__device__ __forceinline__ uint32_t pack2(float a, float b) {
    __nv_bfloat162 p = __floats2bfloat162_rn(a, b);
    return *reinterpret_cast<uint32_t*>(&p);
}

// ---------------------------------------------------------------------------
// xa partials
// ---------------------------------------------------------------------------
__global__ __launch_bounds__(256)
void xa_part_kernel(const float* __restrict__ x, const float* __restrict__ A)
{
    __shared__ float As[RNK * KPAD];
    const int tid = threadIdx.x;
    const int m0  = blockIdx.x * 32;
    const int k0  = blockIdx.y * KRANGE;

    for (int j = tid; j < RNK * KRANGE; j += 256) {
        int r = j >> 9, kk = j & 511;
        As[r * KPAD + kk] = A[(size_t)(k0 + kk) * RNK + r];
    }
    __syncthreads();

    const int row  = tid >> 3;
    const int ksub = tid & 7;
    float acc[RNK];
#pragma unroll
    for (int r = 0; r < RNK; r++) acc[r] = 0.f;

    const float* xr = x + (size_t)(m0 + row) * K_TOTAL + k0;
#pragma unroll 4
    for (int i = 0; i < KRANGE / 8; i++) {
        int kk = i * 8 + ksub;
        float xv = xr[kk];
#pragma unroll
        for (int r = 0; r < RNK; r++) acc[r] += xv * As[r * KPAD + kk];
    }
#pragma unroll
    for (int r = 0; r < RNK; r++) {
        acc[r] += __shfl_xor_sync(0xffffffffu, acc[r], 1);
        acc[r] += __shfl_xor_sync(0xffffffffu, acc[r], 2);
        acc[r] += __shfl_xor_sync(0xffffffffu, acc[r], 4);
    }
    if (ksub == 0) {
        float* o = g_xap + ((size_t)blockIdx.y * M_TOTAL + m0 + row) * RNK;
#pragma unroll
        for (int r = 0; r < RNK; r++) o[r] = acc[r];
    }
}

__global__ void xa_combine_kernel()
{
    int j = blockIdx.x * 256 + threadIdx.x;
    float s = 0.f;
#pragma unroll
    for (int p = 0; p < KSPLIT; p++) s += g_xap[p * M_TOTAL * RNK + j];
    g_xa[j] = s;
}

// ---------------------------------------------------------------------------
__global__ void xb_kernel(const float* __restrict__ x)
{
    size_t base = ((size_t)blockIdx.x * 256 + threadIdx.x) * 8;
    float4 v0 = *(const float4*)(x + base);
    float4 v1 = *(const float4*)(x + base + 4);
    uint4 o;
    o.x = pack2(v0.x, v0.y); o.y = pack2(v0.z, v0.w);
    o.z = pack2(v1.x, v1.y); o.w = pack2(v1.z, v1.w);
    *reinterpret_cast<uint4*>(g_xb + base) = o;
}

// ---------------------------------------------------------------------------
// Fused NF4-dequant GEMM (R10 topology: 128 thr, 4 warps, warp 64x32, occ 3).
// B producer: raw idx LDG one chunk ahead -> shfl-LUT convert -> STS.128 into
// double-buffered swizzled B tile. A path: 3-stage cp.async (unchanged).
// ---------------------------------------------------------------------------
#define MMA_BF16(d,a,b0,b1)                                                   \
    asm volatile("mma.sync.aligned.m16n8k16.row.col.f32.bf16.bf16.f32 "       \
        "{%0,%1,%2,%3}, {%4,%5,%6,%7}, {%8,%9}, {%0,%1,%2,%3};\n"             \
        : "+f"(d[0]), "+f"(d[1]), "+f"(d[2]), "+f"(d[3])                      \
        : "r"(a[0]), "r"(a[1]), "r"(a[2]), "r"(a[3]), "r"(b0), "r"(b1))

static __device__ __forceinline__ void ldsm_x4(uint32_t (&d)[4], uint32_t addr) {
    asm volatile("ldmatrix.sync.aligned.m8n8.x4.shared.b16 {%0,%1,%2,%3}, [%4];"
                 : "=r"(d[0]), "=r"(d[1]), "=r"(d[2]), "=r"(d[3]) : "r"(addr));
}
static __device__ __forceinline__ void cpa16(uint32_t saddr, const void* g) {
    asm volatile("cp.async.cg.shared.global [%0], [%1], 16;" :: "r"(saddr), "l"(g) : "memory");
}
static __device__ __forceinline__ void sts128(uint32_t addr, uint32_t a, uint32_t b,
                                              uint32_t c, uint32_t d) {
    asm volatile("st.shared.v4.b32 [%0], {%1,%2,%3,%4};"
                 :: "r"(addr), "r"(a), "r"(b), "r"(c), "r"(d) : "memory");
}
static __device__ __forceinline__ void conv_row(uint32_t dst, int4 q0, int4 q1,
                                                float sc, float lv) {
    float f0 = __shfl_sync(0xffffffffu, lv, q0.x) * sc;
    float f1 = __shfl_sync(0xffffffffu, lv, q0.y) * sc;
    float f2 = __shfl_sync(0xffffffffu, lv, q0.z) * sc;
    float f3 = __shfl_sync(0xffffffffu, lv, q0.w) * sc;
    float f4 = __shfl_sync(0xffffffffu, lv, q1.x) * sc;
    float f5 = __shfl_sync(0xffffffffu, lv, q1.y) * sc;
    float f6 = __shfl_sync(0xffffffffu, lv, q1.z) * sc;
    float f7 = __shfl_sync(0xffffffffu, lv, q1.w) * sc;
    sts128(dst, pack2(f0, f1), pack2(f2, f3), pack2(f4, f5), pack2(f6, f7));
}

__global__ __launch_bounds__(128, 3)
void gemm_kernel(const int* __restrict__ widx, const float* __restrict__ wsc,
                 const float* __restrict__ lB, const float* __restrict__ bias,
                 float* __restrict__ out)
{
    extern __shared__ __align__(128) unsigned char smem[];
    uint32_t sbase;
    asm("{ .reg .u64 t; cvta.to.shared.u64 t, %1; cvt.u32.u64 %0, t; }"
        : "=r"(sbase) : "l"(smem));

    const int tid  = threadIdx.x;
    const int wid  = tid >> 5;
    const int lane = tid & 31;
    const int m0   = blockIdx.x * GM;   // fastest: 4 m-tiles share idx via L2
    const int n0   = blockIdx.y * GN;

    const int wm = wid >> 1;            // 0..1 -> rows wm*64
    const int wn = wid & 1;             // 0..1 -> cols wn*32
    const int s  = lane & 7;
    const int g  = lane >> 3;

    const int ldr = tid >> 3;           // 0..15
    const int ldc = tid & 7;

    const float lv = c_nf4[lane & 15];  // warp-held NF4 LUT

    // swizzled store bases; rows step 16 -> XOR key (ldr&7) invariant
    const uint32_t swoff = (uint32_t)(ldr * 128 + ((ldc ^ (ldr & 7)) << 4));
    const uint32_t dstA  = sbase + swoff;
    const uint32_t dstB  = sbase + SB_OFF + swoff;

    const __nv_bfloat16* gA  = g_xb + (size_t)(m0 + ldr) * K_TOTAL + ldc * 8;
    const int*           gI  = widx + (size_t)(n0 + ldr) * K_TOTAL + ldc * 8;
    const float*         gS  = wsc  + (size_t)(n0 + ldr) * 64;

    int aRow[4], bRow[2];
#pragma unroll
    for (int i = 0; i < 4; i++)
        aRow[i] = (wm * 64 + i * 16 + (g & 1) * 8 + (lane & 7)) * 128;
    const int agk = g >> 1;
#pragma unroll
    for (int p = 0; p < 2; p++)
        bRow[p] = (wn * 32 + p * 16 + (g >> 1) * 8 + (lane & 7)) * 128;
    const int bgk = g & 1;

    float acc[4][4][4];
#pragma unroll
    for (int i = 0; i < 4; i++)
#pragma unroll
        for (int j = 0; j < 4; j++)
#pragma unroll
            for (int e = 0; e < 4; e++) acc[i][j][e] = 0.f;

    int4  q[4][2];
    float bs[4];

    // ---- prologue: A stages 0,1 ----
#pragma unroll
    for (int st = 0; st < 2; st++) {
        uint32_t dA = dstA + st * A_BYTES;
#pragma unroll
        for (int i = 0; i < 8; i++)
            cpa16(dA + i * 2048, gA + st * KC + (size_t)i * 16 * K_TOTAL);
        asm volatile("cp.async.commit_group;" ::: "memory");
    }
    // B chunk 0: load raw + convert into buffer 0
#pragma unroll
    for (int i = 0; i < 4; i++) {
        const int* p = gI + (size_t)i * 16 * K_TOTAL;
        q[i][0] = ((const int4*)p)[0];
        q[i][1] = ((const int4*)p)[1];
        bs[i] = __ldg(gS + i * 1024);
    }
#pragma unroll
    for (int i = 0; i < 4; i++)
        conv_row(dstB + i * 2048, q[i][0], q[i][1], bs[i], lv);
    // B chunk 1: raw into regs
#pragma unroll
    for (int i = 0; i < 4; i++) {
        const int* p = gI + KC + (size_t)i * 16 * K_TOTAL;
        q[i][0] = ((const int4*)p)[0];
        q[i][1] = ((const int4*)p)[1];
        bs[i] = __ldg(gS + i * 1024 + 1);
    }

    const __nv_bfloat16* gAp = gA + 2 * KC;
    const int*           gIp = gI + 2 * KC;

    for (int ic = 0; ic < NCH; ic++) {
        asm volatile("cp.async.wait_group 1;" ::: "memory");
        __syncthreads();

        // convert chunk ic+1 (regs) into the other B buffer
        if (ic + 1 < NCH) {
            uint32_t dB = dstB + ((ic + 1) & 1) * B_BYTES;
#pragma unroll
            for (int i = 0; i < 4; i++)
                conv_row(dB + i * 2048, q[i][0], q[i][1], bs[i], lv);
        }
        // prefetch chunk ic+2: A via cp.async, B raw via LDG (hidden by MMAs)
        if (ic + 2 < NCH) {
            uint32_t dA = dstA + ((ic + 2) % A_STAGES) * A_BYTES;
#pragma unroll
            for (int i = 0; i < 8; i++)
                cpa16(dA + i * 2048, gAp + (size_t)i * 16 * K_TOTAL);
            gAp += KC;
#pragma unroll
            for (int i = 0; i < 4; i++) {
                const int* p = gIp + (size_t)i * 16 * K_TOTAL;
                q[i][0] = ((const int4*)p)[0];
                q[i][1] = ((const int4*)p)[1];
                bs[i] = __ldg(gS + i * 1024 + ic + 2);
            }
            gIp += KC;
        }
        asm volatile("cp.async.commit_group;" ::: "memory");

        // compute chunk ic
        uint32_t sA = sbase + (ic % A_STAGES) * A_BYTES;
        uint32_t sB = sbase + SB_OFF + (ic & 1) * B_BYTES;
#pragma unroll
        for (int ks = 0; ks < 4; ks++) {
            uint32_t a[4][4], b[2][4];
#pragma unroll
            for (int i = 0; i < 4; i++)
                ldsm_x4(a[i], sA + aRow[i] + (((ks * 2 + agk) ^ s) << 4));
#pragma unroll
            for (int p = 0; p < 2; p++)
                ldsm_x4(b[p], sB + bRow[p] + (((ks * 2 + bgk) ^ s) << 4));
#pragma unroll
            for (int i = 0; i < 4; i++) {
                MMA_BF16(acc[i][0], a[i], b[0][0], b[0][1]);
                MMA_BF16(acc[i][1], a[i], b[0][2], b[0][3]);
                MMA_BF16(acc[i][2], a[i], b[1][0], b[1][1]);
                MMA_BF16(acc[i][3], a[i], b[1][2], b[1][3]);
            }
        }
    }

    // ---------------- epilogue ----------------
    __syncthreads();
    float* lBs    = reinterpret_cast<float*>(smem);                 // [16][64]
    float* xa_s   = lBs + RNK * GN;                                 // [128][16]
    float* bias_s = xa_s + GM * RNK;                                // [64]
    for (int j = tid; j < RNK * GN; j += 128) {
        int r = j >> 6, c = j & 63;
        lBs[j] = lB[(size_t)r * N_TOTAL + n0 + c];
    }
    for (int j = tid; j < GM * RNK; j += 128) xa_s[j] = g_xa[m0 * RNK + j];
    if (tid < GN) bias_s[tid] = bias[n0 + tid];
    __syncthreads();

    const int qr = lane >> 2;
    const int qc = (lane & 3) * 2;
#pragma unroll
    for (int i = 0; i < 4; i++) {
        int rlo = wm * 64 + i * 16 + qr;
        int rhi = rlo + 8;
        float xal[RNK], xah[RNK];
#pragma unroll
        for (int r = 0; r < RNK; r++) { xal[r] = xa_s[rlo * RNK + r]; xah[r] = xa_s[rhi * RNK + r]; }
#pragma unroll
        for (int j = 0; j < 4; j++) {
            int nc = wn * 32 + j * 8 + qc;
            float l00 = 0.f, l01 = 0.f, l10 = 0.f, l11 = 0.f;
#pragma unroll
            for (int r = 0; r < RNK; r++) {
                float b0 = lBs[r * GN + nc], b1 = lBs[r * GN + nc + 1];
                l00 += xal[r] * b0; l01 += xal[r] * b1;
                l10 += xah[r] * b0; l11 += xah[r] * b1;
            }
            float bv0 = bias_s[nc], bv1 = bias_s[nc + 1];
            float2 r0, r1;
            r0.x = acc[i][j][0] + bv0 + 2.0f * l00;
            r0.y = acc[i][j][1] + bv1 + 2.0f * l01;
            r1.x = acc[i][j][2] + bv0 + 2.0f * l10;
            r1.y = acc[i][j][3] + bv1 + 2.0f * l11;
            *(float2*)&out[(size_t)(m0 + rlo) * N_TOTAL + n0 + nc] = r0;
            *(float2*)&out[(size_t)(m0 + rhi) * N_TOTAL + n0 + nc] = r1;
        }
    }
}

// ---------------------------------------------------------------------------
extern "C" void kernel_launch(void* const* d_in, const int* in_sizes, int n_in,
                              void* d_out, int out_size)
{
    (void)in_sizes; (void)n_in; (void)out_size;
    const float* x    = (const float*)d_in[0];
    const int*   widx = (const int*)  d_in[1];
    const float* wsc  = (const float*)d_in[2];
    const float* lA   = (const float*)d_in[3];
    const float* lB   = (const float*)d_in[4];
    const float* bias = (const float*)d_in[5];
    float* out = (float*)d_out;

    xa_part_kernel<<<dim3(M_TOTAL / 32, KSPLIT), 256>>>(x, lA);
    xa_combine_kernel<<<(M_TOTAL * RNK) / 256, 256>>>();
    xb_kernel<<<(M_TOTAL * K_TOTAL) / (256 * 8), 256>>>(x);

    cudaFuncSetAttribute(gemm_kernel, cudaFuncAttributeMaxDynamicSharedMemorySize, SMEM_TOTAL);
    gemm_kernel<<<dim3(M_TOTAL / GM, N_TOTAL / GN), 128, SMEM_TOTAL>>>(
        widx, wsc, lB, bias, out);
}

// round 13
// speedup vs baseline: 1.6968x; 1.6968x over previous
#include <cuda_runtime.h>
#include <cuda_bf16.h>
#include <stdint.h>

#define K_TOTAL 4096
#define N_TOTAL 11008
#define M_TOTAL 512
#define RNK 16

// ---- GEMM tiling ----
#define GM 128
#define GN 64
#define KC 64
#define NCH (K_TOTAL / KC)          /* 64 */
#define STAGES 3
#define A_BYTES (GM * KC * 2)       /* 16384 */
#define B_BYTES (GN * KC * 2)       /* 8192 */
#define STAGE_BYTES (A_BYTES + B_BYTES)          /* 24576 */
#define SMEM_TOTAL (STAGES * STAGE_BYTES)        /* 73728 */

// ---- xa split-K ----
#define KSPLIT 8
#define KRANGE (K_TOTAL / KSPLIT)   /* 512 */
#define KPAD 520

// ---- scratch ----
__device__ __align__(256) __nv_bfloat16 g_w[(size_t)N_TOTAL * K_TOTAL];  // 90MB dequant W
__device__ __align__(256) __nv_bfloat16 g_xb[(size_t)M_TOTAL * K_TOTAL]; // 4MB x bf16
__device__ __align__(256) float g_xap[KSPLIT * M_TOTAL * RNK];
__device__ __align__(256) float g_xa[M_TOTAL * RNK];

__constant__ float c_nf4[16] = {
    -1.0f, -0.6961928009986877f, -0.5250730514526367f, -0.39491748809814453f,
    -0.28444138169288635f, -0.18477343022823334f, -0.09105003625154495f, 0.0f,
    0.07958029955625534f, 0.16093020141124725f, 0.24611230194568634f,
    0.33791524171829224f, 0.44070982933044434f, 0.5626170039176941f,
    0.7229568362236023f, 1.0f };

__device__ __forceinline__ uint32_t pack2(float a, float b) {
    __nv_bfloat162 p = __floats2bfloat162_rn(a, b);
    return *reinterpret_cast<uint32_t*>(&p);
}

// ---------------------------------------------------------------------------
// xa partials
// ---------------------------------------------------------------------------
__global__ __launch_bounds__(256)
void xa_part_kernel(const float* __restrict__ x, const float* __restrict__ A)
{
    __shared__ float As[RNK * KPAD];
    const int tid = threadIdx.x;
    const int m0  = blockIdx.x * 32;
    const int k0  = blockIdx.y * KRANGE;

    for (int j = tid; j < RNK * KRANGE; j += 256) {
        int r = j >> 9, kk = j & 511;
        As[r * KPAD + kk] = A[(size_t)(k0 + kk) * RNK + r];
    }
    __syncthreads();

    const int row  = tid >> 3;
    const int ksub = tid & 7;
    float acc[RNK];
#pragma unroll
    for (int r = 0; r < RNK; r++) acc[r] = 0.f;

    const float* xr = x + (size_t)(m0 + row) * K_TOTAL + k0;
#pragma unroll 4
    for (int i = 0; i < KRANGE / 8; i++) {
        int kk = i * 8 + ksub;
        float xv = xr[kk];
#pragma unroll
        for (int r = 0; r < RNK; r++) acc[r] += xv * As[r * KPAD + kk];
    }
#pragma unroll
    for (int r = 0; r < RNK; r++) {
        acc[r] += __shfl_xor_sync(0xffffffffu, acc[r], 1);
        acc[r] += __shfl_xor_sync(0xffffffffu, acc[r], 2);
        acc[r] += __shfl_xor_sync(0xffffffffu, acc[r], 4);
    }
    if (ksub == 0) {
        float* o = g_xap + ((size_t)blockIdx.y * M_TOTAL + m0 + row) * RNK;
#pragma unroll
        for (int r = 0; r < RNK; r++) o[r] = acc[r];
    }
}

__global__ void xa_combine_kernel()
{
    int j = blockIdx.x * 256 + threadIdx.x;
    float s = 0.f;
#pragma unroll
    for (int p = 0; p < KSPLIT; p++) s += g_xap[p * M_TOTAL * RNK + j];
    g_xa[j] = s;
}

// ---------------------------------------------------------------------------
__global__ void xb_kernel(const float* __restrict__ x)
{
    size_t base = ((size_t)blockIdx.x * 256 + threadIdx.x) * 8;
    float4 v0 = *(const float4*)(x + base);
    float4 v1 = *(const float4*)(x + base + 4);
    uint4 o;
    o.x = pack2(v0.x, v0.y); o.y = pack2(v0.z, v0.w);
    o.z = pack2(v1.x, v1.y); o.w = pack2(v1.z, v1.w);
    *reinterpret_cast<uint4*>(g_xb + base) = o;
}

// ---------------------------------------------------------------------------
__global__ void dequant_kernel(const int* __restrict__ widx, const float* __restrict__ wsc)
{
    size_t base = ((size_t)blockIdx.x * 256 + threadIdx.x) * 16;
    int lane = threadIdx.x & 31;
    float lv = c_nf4[lane & 15];
    float s = wsc[base >> 6];
    const int4* ip = reinterpret_cast<const int4*>(widx + base);
    uint32_t o[8];
#pragma unroll
    for (int j = 0; j < 4; j++) {
        int4 v = ip[j];
        float f0 = __shfl_sync(0xffffffffu, lv, v.x) * s;
        float f1 = __shfl_sync(0xffffffffu, lv, v.y) * s;
        float f2 = __shfl_sync(0xffffffffu, lv, v.z) * s;
        float f3 = __shfl_sync(0xffffffffu, lv, v.w) * s;
        o[j * 2]     = pack2(f0, f1);
        o[j * 2 + 1] = pack2(f2, f3);
    }
    uint4* op = reinterpret_cast<uint4*>(g_w + base);
    op[0] = make_uint4(o[0], o[1], o[2], o[3]);
    op[1] = make_uint4(o[4], o[5], o[6], o[7]);
}

// ---------------------------------------------------------------------------
// GEMM: 128 threads, 4 warps, warp tile 64x32, CTA 128x64, occ 3.
// Fragment double-buffering: ldsm for ks+1 overlaps MMAs of ks.
// ---------------------------------------------------------------------------
#define MMA_BF16(d,a,b0,b1)                                                   \
    asm volatile("mma.sync.aligned.m16n8k16.row.col.f32.bf16.bf16.f32 "       \
        "{%0,%1,%2,%3}, {%4,%5,%6,%7}, {%8,%9}, {%0,%1,%2,%3};\n"             \
        : "+f"(d[0]), "+f"(d[1]), "+f"(d[2]), "+f"(d[3])                      \
        : "r"(a[0]), "r"(a[1]), "r"(a[2]), "r"(a[3]), "r"(b0), "r"(b1))

static __device__ __forceinline__ void ldsm_x4(uint32_t (&d)[4], uint32_t addr) {
    asm volatile("ldmatrix.sync.aligned.m8n8.x4.shared.b16 {%0,%1,%2,%3}, [%4];"
                 : "=r"(d[0]), "=r"(d[1]), "=r"(d[2]), "=r"(d[3]) : "r"(addr));
}
static __device__ __forceinline__ void cpa16(uint32_t saddr, const void* g) {
    asm volatile("cp.async.cg.shared.global [%0], [%1], 16;" :: "r"(saddr), "l"(g) : "memory");
}

__global__ __launch_bounds__(128, 3)
void gemm_kernel(const float* __restrict__ lB, const float* __restrict__ bias,
                 float* __restrict__ out)
{
    extern __shared__ __align__(128) unsigned char smem[];
    uint32_t sbase;
    asm("{ .reg .u64 t; cvta.to.shared.u64 t, %1; cvt.u32.u64 %0, t; }"
        : "=r"(sbase) : "l"(smem));

    const int tid  = threadIdx.x;
    const int wid  = tid >> 5;
    const int lane = tid & 31;
    const int m0   = blockIdx.x * GM;   // fastest: 4 m-tiles share B via L2
    const int n0   = blockIdx.y * GN;

    const int wm = wid >> 1;            // 0..1 -> rows wm*64
    const int wn = wid & 1;             // 0..1 -> cols wn*32
    const int s  = lane & 7;
    const int g  = lane >> 3;

    const int ldr = tid >> 3;           // 0..15
    const int ldc = tid & 7;

    const uint32_t dstbase = sbase + (uint32_t)(ldr * 128 + ((ldc ^ (ldr & 7)) << 4));

    const __nv_bfloat16* gA = g_xb + (size_t)(m0 + ldr) * K_TOTAL + ldc * 8;
    const __nv_bfloat16* gB = g_w  + (size_t)(n0 + ldr) * K_TOTAL + ldc * 8;

    int aRow[4], bRow[2];
#pragma unroll
    for (int i = 0; i < 4; i++)
        aRow[i] = (wm * 64 + i * 16 + (g & 1) * 8 + (lane & 7)) * 128;
    const int agk = g >> 1;
#pragma unroll
    for (int p = 0; p < 2; p++)
        bRow[p] = (wn * 32 + p * 16 + (g >> 1) * 8 + (lane & 7)) * 128;
    const int bgk = g & 1;

    float acc[4][4][4];
#pragma unroll
    for (int i = 0; i < 4; i++)
#pragma unroll
        for (int j = 0; j < 4; j++)
#pragma unroll
            for (int e = 0; e < 4; e++) acc[i][j][e] = 0.f;

    // ---- prologue: fill stages 0,1 ----
#pragma unroll
    for (int st = 0; st < STAGES - 1; st++) {
        uint32_t dA = dstbase + st * STAGE_BYTES;
        uint32_t dB = dA + A_BYTES;
#pragma unroll
        for (int i = 0; i < 8; i++)
            cpa16(dA + i * 2048, gA + st * KC + (size_t)i * 16 * K_TOTAL);
#pragma unroll
        for (int i = 0; i < 4; i++)
            cpa16(dB + i * 2048, gB + st * KC + (size_t)i * 16 * K_TOTAL);
        asm volatile("cp.async.commit_group;" ::: "memory");
    }

    const __nv_bfloat16* gAp = gA + 2 * KC;
    const __nv_bfloat16* gBp = gB + 2 * KC;

    for (int ic = 0; ic < NCH; ic++) {
        asm volatile("cp.async.wait_group 1;" ::: "memory");
        __syncthreads();

        if (ic + 2 < NCH) {
            uint32_t dA = dstbase + ((ic + 2) % STAGES) * STAGE_BYTES;
            uint32_t dB = dA + A_BYTES;
#pragma unroll
            for (int i = 0; i < 8; i++)
                cpa16(dA + i * 2048, gAp + (size_t)i * 16 * K_TOTAL);
#pragma unroll
            for (int i = 0; i < 4; i++)
                cpa16(dB + i * 2048, gBp + (size_t)i * 16 * K_TOTAL);
            gAp += KC;
            gBp += KC;
        }
        asm volatile("cp.async.commit_group;" ::: "memory");

        uint32_t sA = sbase + (ic % STAGES) * STAGE_BYTES, sB = sA + A_BYTES;

        // fragment double-buffer: preload ks=0, prefetch ks+1 during MMAs
        uint32_t a[2][4][4], b[2][2][4];
#pragma unroll
        for (int i = 0; i < 4; i++)
            ldsm_x4(a[0][i], sA + aRow[i] + ((agk ^ s) << 4));
#pragma unroll
        for (int p = 0; p < 2; p++)
            ldsm_x4(b[0][p], sB + bRow[p] + ((bgk ^ s) << 4));

#pragma unroll
        for (int ks = 0; ks < 4; ks++) {
            const int cur = ks & 1, nxt = cur ^ 1;
            if (ks < 3) {
#pragma unroll
                for (int i = 0; i < 4; i++)
                    ldsm_x4(a[nxt][i], sA + aRow[i] + ((((ks + 1) * 2 + agk) ^ s) << 4));
#pragma unroll
                for (int p = 0; p < 2; p++)
                    ldsm_x4(b[nxt][p], sB + bRow[p] + ((((ks + 1) * 2 + bgk) ^ s) << 4));
            }
#pragma unroll
            for (int i = 0; i < 4; i++) {
                MMA_BF16(acc[i][0], a[cur][i], b[cur][0][0], b[cur][0][1]);
                MMA_BF16(acc[i][1], a[cur][i], b[cur][0][2], b[cur][0][3]);
                MMA_BF16(acc[i][2], a[cur][i], b[cur][1][0], b[cur][1][1]);
                MMA_BF16(acc[i][3], a[cur][i], b[cur][1][2], b[cur][1][3]);
            }
        }
    }

    // ---------------- epilogue ----------------
    __syncthreads();
    float* lBs    = reinterpret_cast<float*>(smem);                 // [16][64]
    float* xa_s   = lBs + RNK * GN;                                 // [128][16]
    float* bias_s = xa_s + GM * RNK;                                // [64]
    for (int j = tid; j < RNK * GN; j += 128) {
        int r = j >> 6, c = j & 63;
        lBs[j] = lB[(size_t)r * N_TOTAL + n0 + c];
    }
    for (int j = tid; j < GM * RNK; j += 128) xa_s[j] = g_xa[m0 * RNK + j];
    if (tid < GN) bias_s[tid] = bias[n0 + tid];
    __syncthreads();

    const int qr = lane >> 2;
    const int qc = (lane & 3) * 2;
#pragma unroll
    for (int i = 0; i < 4; i++) {
        int rlo = wm * 64 + i * 16 + qr;
        int rhi = rlo + 8;
        float xal[RNK], xah[RNK];
#pragma unroll
        for (int r = 0; r < RNK; r++) { xal[r] = xa_s[rlo * RNK + r]; xah[r] = xa_s[rhi * RNK + r]; }
#pragma unroll
        for (int j = 0; j < 4; j++) {
            int nc = wn * 32 + j * 8 + qc;
            float l00 = 0.f, l01 = 0.f, l10 = 0.f, l11 = 0.f;
#pragma unroll
            for (int r = 0; r < RNK; r++) {
                float b0 = lBs[r * GN + nc], b1 = lBs[r * GN + nc + 1];
                l00 += xal[r] * b0; l01 += xal[r] * b1;
                l10 += xah[r] * b0; l11 += xah[r] * b1;
            }
            float bv0 = bias_s[nc], bv1 = bias_s[nc + 1];
            float2 r0, r1;
            r0.x = acc[i][j][0] + bv0 + 2.0f * l00;
            r0.y = acc[i][j][1] + bv1 + 2.0f * l01;
            r1.x = acc[i][j][2] + bv0 + 2.0f * l10;
            r1.y = acc[i][j][3] + bv1 + 2.0f * l11;
            *(float2*)&out[(size_t)(m0 + rlo) * N_TOTAL + n0 + nc] = r0;
            *(float2*)&out[(size_t)(m0 + rhi) * N_TOTAL + n0 + nc] = r1;
        }
    }
}

// ---------------------------------------------------------------------------
extern "C" void kernel_launch(void* const* d_in, const int* in_sizes, int n_in,
                              void* d_out, int out_size)
{
    (void)in_sizes; (void)n_in; (void)out_size;
    const float* x    = (const float*)d_in[0];
    const int*   widx = (const int*)  d_in[1];
    const float* wsc  = (const float*)d_in[2];
    const float* lA   = (const float*)d_in[3];
    const float* lB   = (const float*)d_in[4];
    const float* bias = (const float*)d_in[5];
    float* out = (float*)d_out;

    xa_part_kernel<<<dim3(M_TOTAL / 32, KSPLIT), 256>>>(x, lA);
    xa_combine_kernel<<<(M_TOTAL * RNK) / 256, 256>>>();
    xb_kernel<<<(M_TOTAL * K_TOTAL) / (256 * 8), 256>>>(x);
    dequant_kernel<<<(N_TOTAL * K_TOTAL) / (256 * 16), 256>>>(widx, wsc);

    cudaFuncSetAttribute(gemm_kernel, cudaFuncAttributeMaxDynamicSharedMemorySize, SMEM_TOTAL);
    gemm_kernel<<<dim3(M_TOTAL / GM, N_TOTAL / GN), 128, SMEM_TOTAL>>>(lB, bias, out);
}